// round 15
// baseline (speedup 1.0000x reference)
#include <cuda_runtime.h>
#include <cuda_bf16.h>
#include <cstdint>

// ---------------------------------------------------------------------------
// 4-layer LIF SNN scan (B=4096, S=H=256, T=50, A=2) on sm_103a.  R15:
//  FUSED kernel: the P1 (= x_t @ W1, exact ascending-k FFMA chain) is computed
//  INSIDE the scan kernel as a phase at the end of step t (for t+1), filling
//  the scan's latency slack. P1 values live in registers and feed L1 directly
//  (no g_P1 gmem round-trip, no separate P1 launch).
//  - W ring: KC=16 double buffer (fits 225KB smem with 28-row u states).
//  - x: cp.async double buffer, staged 2 steps ahead.
//  - All arithmetic chains verbatim the proven bit-exact code.
// ---------------------------------------------------------------------------

namespace {

constexpr int Bb = 4096;
constexpr int Ss = 256;
constexpr int Tt = 50;
constexpr int Hh = 256;
constexpr int Aa = 2;

constexpr int MB   = 28;
constexpr int NBLK = (Bb + MB - 1) / MB;     // 147

constexpr float CDECAY = 0.5f;
constexpr float VDECAY = 0.75f;
constexpr float VTH    = 0.5f;

constexpr int SC_THREADS = 512;              // 16 warps; warp w owns N-cols [16w,16w+16)
constexpr int AP = 264;                      // bf16 tile row stride
constexpr int XP = 260;                      // x tile row stride (floats)

constexpr int KC = 16;                       // W rows per chunk
constexpr int NCHUNK = Hh / KC;              // 16
constexpr int WROWB = 48;                    // staged row stride (32B data + 16 pad)
constexpr int WSPB  = 256 * WROWB;           // 12,288 per split
constexpr int WCHUNK = 3 * WSPB;             // 36,864

// smem offsets (bytes)
constexpr int OFF_WR  = 0;                   // ring [2][3][256][WROWB]  73,728
constexpr int OFF_TA  = 73728;               // bf16 [32][AP]            16,896
constexpr int OFF_TB  = 90624;               // bf16 [32][AP]            16,896
constexpr int OFF_U2  = 107520;              // f32 [28][256]            28,672
constexpr int OFF_U3  = 136192;              // f32 [28][256]            28,672
constexpr int OFF_W4S = 164864;              // f32 [512]                 2,048
constexpr int OFF_XB  = 166912;              // f32 [2][28][XP]          58,240
constexpr int SC_SMEM = 225152;

}  // namespace

__device__ __nv_bfloat16 g_Ws[2][3][Hh * Hh];   // [layer][split][n*256+k]

// ---------------- PTX helpers ----------------
__device__ __forceinline__ void cpa16(uint32_t dst_s, const void* src_g) {
    asm volatile("cp.async.cg.shared.global [%0], [%1], 16;\n" :: "r"(dst_s), "l"(src_g));
}
__device__ __forceinline__ void cpa4(uint32_t dst_s, const void* src_g) {
    asm volatile("cp.async.ca.shared.global [%0], [%1], 4;\n" :: "r"(dst_s), "l"(src_g));
}
__device__ __forceinline__ void cpa_commit() { asm volatile("cp.async.commit_group;\n"); }
__device__ __forceinline__ void cpa_wait0()  { asm volatile("cp.async.wait_group 0;\n" ::: "memory"); }
__device__ __forceinline__ void ldsm_x4(uint32_t r[4], uint32_t a) {
    asm volatile("ldmatrix.sync.aligned.m8n8.x4.shared.b16 {%0,%1,%2,%3}, [%4];"
                 : "=r"(r[0]), "=r"(r[1]), "=r"(r[2]), "=r"(r[3]) : "r"(a));
}
__device__ __forceinline__ void ldsm_x2(uint32_t r[2], uint32_t a) {
    asm volatile("ldmatrix.sync.aligned.m8n8.x2.shared.b16 {%0,%1}, [%2];"
                 : "=r"(r[0]), "=r"(r[1]) : "r"(a));
}
__device__ __forceinline__ void mma16816(float c[4], const uint32_t a[4], const uint32_t b[2]) {
    asm volatile(
        "mma.sync.aligned.m16n8k16.row.col.f32.bf16.bf16.f32 "
        "{%0,%1,%2,%3}, {%4,%5,%6,%7}, {%8,%9}, {%0,%1,%2,%3};"
        : "+f"(c[0]), "+f"(c[1]), "+f"(c[2]), "+f"(c[3])
        : "r"(a[0]), "r"(a[1]), "r"(a[2]), "r"(a[3]), "r"(b[0]), "r"(b[1]));
}

// ---------------- K1: exact bf16 3-split of W2/W3 (transposed) ----------------
__global__ void split_w(const float* __restrict__ w2, const float* __restrict__ w3) {
    const int layer = blockIdx.y;
    const int idx = blockIdx.x * blockDim.x + threadIdx.x;
    if (idx >= Hh * Hh) return;
    const int n = idx / Hh, k = idx % Hh;
    const float w = (layer == 0 ? w2 : w3)[k * Hh + n];
    const __nv_bfloat16 h0 = __float2bfloat16(w);
    const float r1 = __fsub_rn(w, __bfloat162float(h0));
    const __nv_bfloat16 h1 = __float2bfloat16(r1);
    const float r2 = __fsub_rn(r1, __bfloat162float(h1));
    g_Ws[layer][0][n * Hh + k] = h0;
    g_Ws[layer][1][n * Hh + k] = h1;
    g_Ws[layer][2][n * Hh + k] = __float2bfloat16(r2);
}

// Per-warp W staging (KC=16): warp w copies B-rows [16w,16w+16) of all 3
// splits: 96 cp.async of 16B -> 3 per lane.
__device__ __forceinline__ void stage_w_warp(const __nv_bfloat16* __restrict__ Wg,
                                             int k0, uint32_t wbuf, int wid, int lane) {
#pragma unroll
    for (int i = 0; i < 3; ++i) {
        const int idx = lane + 32 * i;          // 0..95
        const int sp  = idx >> 5;
        const int rem = idx & 31;
        const int n   = wid * 16 + (rem >> 1);
        const int half = rem & 1;
        cpa16(wbuf + sp * WSPB + n * WROWB + half * 16,
              Wg + sp * (Hh * Hh) + n * Hh + k0 + half * 8);
    }
    cpa_commit();
}

// One mma GEMM + LIF layer (KC=16). Numerics verbatim R10: per-k16 zeroed
// partial mma for split0 + Kahan; splits 1,2 into one residual accumulator.
// u state only for rows < MB; tile rows 28-31 stay zero (deterministic).
__device__ __forceinline__ void gemm_lif_layer(
    const __nv_bfloat16* __restrict__ Wg,
    const __nv_bfloat16* __restrict__ WgNext,
    const float* __restrict__ bias_g,
    const __nv_bfloat16* tileIn, __nv_bfloat16* tileOut,
    float* __restrict__ u_s, float (&vm)[16],
    uint32_t wr0, int wid, int lane)
{
    float acc0[2][2][4], comp[2][2][4], acc12[2][2][4];
#pragma unroll
    for (int m = 0; m < 2; ++m)
#pragma unroll
        for (int n8 = 0; n8 < 2; ++n8)
#pragma unroll
            for (int i = 0; i < 4; ++i) {
                acc0[m][n8][i] = 0.f; comp[m][n8][i] = 0.f; acc12[m][n8][i] = 0.f;
            }

    const int a_row = lane & 15;
    const int a_kc  = (lane >> 4) << 3;
    const int b_nrow = lane & 7;
    const int b_half = ((lane >> 3) & 1) * 16;   // bytes

    for (int c = 0; c < NCHUNK; ++c) {
        cpa_wait0();
        __syncwarp();
        if (c + 1 < NCHUNK)         stage_w_warp(Wg,     (c + 1) * KC, wr0 + ((c + 1) & 1) * WCHUNK, wid, lane);
        else if (WgNext != nullptr) stage_w_warp(WgNext, 0,            wr0,                          wid, lane);

        const uint32_t wbuf = wr0 + (c & 1) * WCHUNK;
        const int k16 = c * KC;

        uint32_t a[2][4];
#pragma unroll
        for (int m = 0; m < 2; ++m)
            ldsm_x4(a[m], (uint32_t)__cvta_generic_to_shared(
                tileIn + (m * 16 + a_row) * AP + (k16 + a_kc)));

#pragma unroll
        for (int n8 = 0; n8 < 2; ++n8) {
            const int nrow = wid * 16 + n8 * 8 + b_nrow;
            {   // split 0: zeroed partial + Kahan
                uint32_t b[2];
                ldsm_x2(b, wbuf + 0 * WSPB + nrow * WROWB + b_half);
#pragma unroll
                for (int m = 0; m < 2; ++m) {
                    float cp[4] = {0.f, 0.f, 0.f, 0.f};
                    mma16816(cp, a[m], b);
#pragma unroll
                    for (int i = 0; i < 4; ++i) {
                        const float y  = __fsub_rn(cp[i], comp[m][n8][i]);
                        const float ts = __fadd_rn(acc0[m][n8][i], y);
                        comp[m][n8][i] = __fsub_rn(__fsub_rn(ts, acc0[m][n8][i]), y);
                        acc0[m][n8][i] = ts;
                    }
                }
            }
            {   // split 1
                uint32_t b[2];
                ldsm_x2(b, wbuf + 1 * WSPB + nrow * WROWB + b_half);
                mma16816(acc12[0][n8], a[0], b);
                mma16816(acc12[1][n8], a[1], b);
            }
            {   // split 2
                uint32_t b[2];
                ldsm_x2(b, wbuf + 2 * WSPB + nrow * WROWB + b_half);
                mma16816(acc12[0][n8], a[0], b);
                mma16816(acc12[1][n8], a[1], b);
            }
        }
    }

#pragma unroll
    for (int m = 0; m < 2; ++m)
#pragma unroll
        for (int n8 = 0; n8 < 2; ++n8)
#pragma unroll
            for (int i = 0; i < 4; ++i) {
                const int row = m * 16 + (lane >> 2) + ((i & 2) ? 8 : 0);
                if (row < MB) {
                    const int col = wid * 16 + n8 * 8 + (lane & 3) * 2 + (i & 1);
                    const int vi  = (m * 2 + n8) * 4 + i;
                    const float small = __fsub_rn(acc12[m][n8][i], comp[m][n8][i]);
                    const float dot   = __fadd_rn(acc0[m][n8][i], small);
                    const float u  = u_s[row * 256 + col];
                    const float bi = __ldg(bias_g + col);
                    const float cur  = __fadd_rn(__fadd_rn(__fmul_rn(u, CDECAY), dot), bi);
                    const float volt = __fadd_rn(vm[vi], cur);
                    const float s    = (volt > VTH) ? 1.0f : 0.0f;
                    u_s[row * 256 + col] = cur;
                    vm[vi] = __fmul_rn(__fmul_rn(volt, VDECAY), __fsub_rn(1.0f, s));
                    tileOut[row * AP + col] = __float2bfloat16(s);
                }
            }
}

// ---------------- K2: fused scan + in-kernel P1 ----------------
__global__ void __launch_bounds__(SC_THREADS, 1) snn_fused(
    const float* __restrict__ x,  const float* __restrict__ w1,
    const float* __restrict__ b1, const float* __restrict__ b2,
    const float* __restrict__ b3,
    const float* __restrict__ w4, const float* __restrict__ b4,
    float* __restrict__ out)
{
    extern __shared__ char smem[];
    __nv_bfloat16* tileA = reinterpret_cast<__nv_bfloat16*>(smem + OFF_TA);
    __nv_bfloat16* tileB = reinterpret_cast<__nv_bfloat16*>(smem + OFF_TB);
    float* u2s = reinterpret_cast<float*>(smem + OFF_U2);
    float* u3s = reinterpret_cast<float*>(smem + OFF_U3);
    float* w4s = reinterpret_cast<float*>(smem + OFF_W4S);
    float* xb  = reinterpret_cast<float*>(smem + OFF_XB);      // [2][MB][XP]
    const uint32_t wr0  = (uint32_t)__cvta_generic_to_shared(smem + OFF_WR);
    const uint32_t xb_s = (uint32_t)__cvta_generic_to_shared(xb);

    const int tid  = threadIdx.x;
    const int wid  = tid >> 5;
    const int lane = tid & 31;
    const int b0   = blockIdx.x * MB;

    // L1/P1 mapping: thread owns cols {j0, j0+1} x rows [row0, row0+7)
    const int cp   = tid & 127;
    const int rg   = tid >> 7;          // 0..3
    const int j0   = cp * 2;
    const int row0 = rg * 7;

    // ---- init ----
    for (int i = tid; i < MB * 256; i += SC_THREADS) { u2s[i] = 0.0f; u3s[i] = 0.0f; }
    for (int i = tid; i < 32 * AP; i += SC_THREADS) {
        tileA[i] = __float2bfloat16(0.0f);
        tileB[i] = __float2bfloat16(0.0f);
    }
    w4s[tid] = __ldg(w4 + tid);   // Hh*Aa == 512

    float vm1[7][2], u1[7][2], vm2[16], vm3[16];
#pragma unroll
    for (int r = 0; r < 7; ++r) { vm1[r][0] = 0.f; vm1[r][1] = 0.f; u1[r][0] = 0.f; u1[r][1] = 0.f; }
#pragma unroll
    for (int i = 0; i < 16; ++i) { vm2[i] = 0.0f; vm3[i] = 0.0f; }

    const float2 bias1 = *reinterpret_cast<const float2*>(b1 + j0);

    const int l4b = tid >> 1, l4a = tid & 1;
    float u4 = 0.f, v4m = 0.f, s4sum = 0.f, bias4 = 0.f;
    if (tid < MB * Aa) bias4 = __ldg(b4 + l4a);

    // cp.async stage of x[:, :, t] into xbuf half `par` (4B strided loads).
    auto stage_x = [&](int t, int par) {
#pragma unroll
        for (int i = 0; i < (MB * Ss) / SC_THREADS; ++i) {
            const int idx = tid + i * SC_THREADS;
            const int r = idx >> 8, s = idx & 255;
            int bg = b0 + r; if (bg >= Bb) bg = Bb - 1;
            cpa4(xb_s + (uint32_t)((par * MB * XP + r * XP + s) * 4),
                 &x[((size_t)bg * Ss + s) * (size_t)Tt + t]);
        }
        cpa_commit();
    };

    // P1 for one timestep from xbuf half `par` -> p1acc (exact ascending-k).
    float p1acc[7][2];
    auto compute_p1 = [&](int par) {
#pragma unroll
        for (int r = 0; r < 7; ++r) { p1acc[r][0] = 0.0f; p1acc[r][1] = 0.0f; }
        const float* xc = xb + par * MB * XP;
        for (int k4 = 0; k4 < Hh / 4; ++k4) {
            float2 wk[4];
#pragma unroll
            for (int kk = 0; kk < 4; ++kk)
                wk[kk] = __ldg(reinterpret_cast<const float2*>(
                    w1 + (size_t)(k4 * 4 + kk) * 256 + j0));
#pragma unroll
            for (int r = 0; r < 7; ++r) {
                const float4 p = *reinterpret_cast<const float4*>(
                    xc + (row0 + r) * XP + k4 * 4);
                float a0 = p1acc[r][0], a1 = p1acc[r][1];
                a0 = __fmaf_rn(p.x, wk[0].x, a0);  a1 = __fmaf_rn(p.x, wk[0].y, a1);
                a0 = __fmaf_rn(p.y, wk[1].x, a0);  a1 = __fmaf_rn(p.y, wk[1].y, a1);
                a0 = __fmaf_rn(p.z, wk[2].x, a0);  a1 = __fmaf_rn(p.z, wk[2].y, a1);
                a0 = __fmaf_rn(p.w, wk[3].x, a0);  a1 = __fmaf_rn(p.w, wk[3].y, a1);
                p1acc[r][0] = a0; p1acc[r][1] = a1;
            }
        }
    };

    // ---- prologue: x(0) staged+visible, x(1) in flight, W L2-chunk0, P1(0) ----
    stage_x(0, 0);
    cpa_wait0();
    stage_x(1, 1);
    stage_w_warp(&g_Ws[0][0][0], 0, wr0, wid, lane);
    __syncthreads();           // x(0) visible block-wide
    compute_p1(0);

    for (int t = 0; t < Tt; ++t) {
        __nv_bfloat16* bufIn  = (t & 1) ? tileB : tileA;
        __nv_bfloat16* bufTmp = (t & 1) ? tileA : tileB;

        // ---- L1 (exact): cur = u*0.5 + P1(regs) + b1 ----
#pragma unroll
        for (int r = 0; r < 7; ++r) {
            const int row = row0 + r;
            float s2[2];
#pragma unroll
            for (int c = 0; c < 2; ++c) {
                const float bi = (c == 0) ? bias1.x : bias1.y;
                const float cur  = __fadd_rn(__fadd_rn(__fmul_rn(u1[r][c], CDECAY),
                                                       p1acc[r][c]), bi);
                const float volt = __fadd_rn(vm1[r][c], cur);
                s2[c] = (volt > VTH) ? 1.0f : 0.0f;
                u1[r][c] = cur;
                vm1[r][c] = __fmul_rn(__fmul_rn(volt, VDECAY), __fsub_rn(1.0f, s2[c]));
            }
            __nv_bfloat162 sp;
            sp.x = __float2bfloat16(s2[0]);
            sp.y = __float2bfloat16(s2[1]);
            *reinterpret_cast<__nv_bfloat162*>(bufIn + row * AP + j0) = sp;
        }
        __syncthreads();   // s1 visible; everyone past last P1-phase/L4

        // Stage x(t+2) into buf[t&1] (x(t) is dead: consumed by P1-phase(t-1)).
        if (t + 2 < Tt) stage_x(t + 2, t & 1);

        gemm_lif_layer(&g_Ws[0][0][0], &g_Ws[1][0][0], b2,
                       bufIn, bufTmp, u2s, vm2, wr0, wid, lane);
        __syncthreads();   // s2 visible

        gemm_lif_layer(&g_Ws[1][0][0], (t + 1 < Tt) ? &g_Ws[0][0][0] : nullptr, b3,
                       bufTmp, bufIn, u3s, vm3, wr0, wid, lane);
        __syncthreads();   // s3 (bufIn) visible; x(t+1) complete + visible

        // ---- P1-phase: compute P1(t+1) from xbuf[(t+1)&1] ----
        if (t + 1 < Tt) compute_p1((t + 1) & 1);

        // ---- L4 (exact): [MB,256]@[256,2] + LIF  (no trailing barrier) ----
        if (tid < MB * Aa) {
            float acc = 0.0f;
            const __nv_bfloat16* row4 = bufIn + l4b * AP;
#pragma unroll 8
            for (int k = 0; k < Hh; ++k)
                acc = __fmaf_rn(__bfloat162float(row4[k]), w4s[k * Aa + l4a], acc);
            const float cur  = __fadd_rn(__fadd_rn(__fmul_rn(u4, CDECAY), acc), bias4);
            const float volt = __fadd_rn(v4m, cur);
            const float s    = (volt > VTH) ? 1.0f : 0.0f;
            u4 = cur;
            v4m = __fmul_rn(__fmul_rn(volt, VDECAY), __fsub_rn(1.0f, s));
            s4sum = __fadd_rn(s4sum, s);
        }
    }

    if (tid < MB * Aa) {
        const int bg = b0 + l4b;
        if (bg < Bb)
            out[bg * Aa + l4a] = __fdiv_rn(__fdiv_rn(s4sum, (float)Tt), (float)Tt);
    }
}

extern "C" void kernel_launch(void* const* d_in, const int* in_sizes, int n_in,
                              void* d_out, int out_size)
{
    const float* x  = (const float*)d_in[0];
    const float* w1 = (const float*)d_in[1];
    const float* b1 = (const float*)d_in[2];
    const float* w2 = (const float*)d_in[3];
    const float* b2 = (const float*)d_in[4];
    const float* w3 = (const float*)d_in[5];
    const float* b3 = (const float*)d_in[6];
    const float* w4 = (const float*)d_in[7];
    const float* b4 = (const float*)d_in[8];
    float* out = (float*)d_out;
    (void)in_sizes; (void)n_in; (void)out_size;

    cudaFuncSetAttribute(snn_fused, cudaFuncAttributeMaxDynamicSharedMemorySize, SC_SMEM);

    split_w<<<dim3((Hh * Hh + 255) / 256, 2), 256>>>(w2, w3);
    snn_fused<<<NBLK, SC_THREADS, SC_SMEM>>>(x, w1, b1, b2, b3, w4, b4, out);
}

// round 16
// speedup vs baseline: 2.1208x; 2.1208x over previous
#include <cuda_runtime.h>
#include <cuda_bf16.h>
#include <cstdint>

// ---------------------------------------------------------------------------
// 4-layer LIF SNN scan (B=4096, S=H=256, T=50, A=2) on sm_103a.  R16:
//  = R14 (best: 2303us, bit-exact) with two scan-only changes:
//   * Kahan per k32 (split-0 mma chained across the chunk's two k16 halves
//     into one zeroed partial) -> half the Kahan FADD traffic on the FMA pipe.
//   * b2/b3 epilogue biases hoisted to registers (no per-step __ldg).
//  P1 and all other arithmetic byte-identical to R14.
// ---------------------------------------------------------------------------

namespace {

constexpr int Bb = 4096;
constexpr int Ss = 256;
constexpr int Tt = 50;
constexpr int Hh = 256;
constexpr int Aa = 2;

constexpr int MB   = 28;
constexpr int NBLK = (Bb + MB - 1) / MB;     // 147

constexpr float CDECAY = 0.5f;
constexpr float VDECAY = 0.75f;
constexpr float VTH    = 0.5f;

// ---- scan geometry ----
constexpr int SC_THREADS = 512;              // 16 warps; warp w owns N-cols [16w,16w+16)
constexpr int AP = 264;                      // bf16 tile row stride

constexpr int KC = 32;                       // W rows per chunk (scan)
constexpr int NCHUNK = Hh / KC;              // 8
constexpr int WROWB = 80;                    // staged row stride bytes
constexpr int WSPB  = 256 * WROWB;           // 20,480 per split
constexpr int WCHUNK = 3 * WSPB;             // 61,440

constexpr int OFF_WR = 0;                    // ring [2][3][256][WROWB] 122,880
constexpr int OFF_TA = 122880;               // bf16 [32][AP] 16,896
constexpr int OFF_TB = 139776;               // bf16 [32][AP] 16,896
constexpr int OFF_U2 = 156672;               // f32 [32][256] 32,768
constexpr int OFF_U3 = 189440;               // f32 [32][256] 32,768
constexpr int OFF_W4S = 222208;              // f32 [512]      2,048
constexpr int SC_SMEM = 224256;

// ---- P1 geometry (R10/R14 verbatim) ----
constexpr int P1_THREADS = 256;
constexpr int P1_KC = 16;
constexpr int P1_SMEM = 2 * MB * 256 * 4 + 2 * P1_KC * 256 * 4;  // 90,112

}  // namespace

__device__ float g_P1[(size_t)Tt * Bb * Hh];            // 210 MB
__device__ __nv_bfloat16 g_Ws[2][3][Hh * Hh];           // [layer][split][n*256+k]

// ---------------- PTX helpers ----------------
__device__ __forceinline__ void cpa16(uint32_t dst_s, const void* src_g) {
    asm volatile("cp.async.cg.shared.global [%0], [%1], 16;\n" :: "r"(dst_s), "l"(src_g));
}
__device__ __forceinline__ void cpa_commit() { asm volatile("cp.async.commit_group;\n"); }
__device__ __forceinline__ void cpa_wait0()  { asm volatile("cp.async.wait_group 0;\n" ::: "memory"); }
__device__ __forceinline__ float ldcs1(const float* p) {
    float r; asm volatile("ld.global.cs.f32 %0, [%1];" : "=f"(r) : "l"(p)); return r;
}
__device__ __forceinline__ void ldsm_x4(uint32_t r[4], uint32_t a) {
    asm volatile("ldmatrix.sync.aligned.m8n8.x4.shared.b16 {%0,%1,%2,%3}, [%4];"
                 : "=r"(r[0]), "=r"(r[1]), "=r"(r[2]), "=r"(r[3]) : "r"(a));
}
__device__ __forceinline__ void ldsm_x2(uint32_t r[2], uint32_t a) {
    asm volatile("ldmatrix.sync.aligned.m8n8.x2.shared.b16 {%0,%1}, [%2];"
                 : "=r"(r[0]), "=r"(r[1]) : "r"(a));
}
__device__ __forceinline__ void mma16816(float c[4], const uint32_t a[4], const uint32_t b[2]) {
    asm volatile(
        "mma.sync.aligned.m16n8k16.row.col.f32.bf16.bf16.f32 "
        "{%0,%1,%2,%3}, {%4,%5,%6,%7}, {%8,%9}, {%0,%1,%2,%3};"
        : "+f"(c[0]), "+f"(c[1]), "+f"(c[2]), "+f"(c[3])
        : "r"(a[0]), "r"(a[1]), "r"(a[2]), "r"(a[3]), "r"(b[0]), "r"(b[1]));
}

// ---------------- K1: exact bf16 3-split of W2/W3 (transposed) ----------------
__global__ void split_w(const float* __restrict__ w2, const float* __restrict__ w3) {
    const int layer = blockIdx.y;
    const int idx = blockIdx.x * blockDim.x + threadIdx.x;
    if (idx >= Hh * Hh) return;
    const int n = idx / Hh, k = idx % Hh;
    const float w = (layer == 0 ? w2 : w3)[k * Hh + n];
    const __nv_bfloat16 h0 = __float2bfloat16(w);
    const float r1 = __fsub_rn(w, __bfloat162float(h0));
    const __nv_bfloat16 h1 = __float2bfloat16(r1);
    const float r2 = __fsub_rn(r1, __bfloat162float(h1));
    g_Ws[layer][0][n * Hh + k] = h0;
    g_Ws[layer][1][n * Hh + k] = h1;
    g_Ws[layer][2][n * Hh + k] = __float2bfloat16(r2);
}

// ---------------- K2: P1 = x_t @ W1 (t-pair), exact ascending-k FFMA ----------
// (R10/R14 verbatim.)
__global__ void __launch_bounds__(P1_THREADS, 2) p1_gemm(
    const float* __restrict__ x, const float* __restrict__ w1)
{
    extern __shared__ float psm[];
    float* xs = psm;                       // [2][28][256]
    float* wr = psm + 2 * MB * 256;        // [2][P1_KC*256]

    const int tid = threadIdx.x;
    const int tp  = blockIdx.y;
    const int b0  = blockIdx.x * MB;
    const int j0   = (tid & 127) * 2;
    const int row0 = (tid >> 7) * 14;

#pragma unroll
    for (int it = 0; it < (MB * Ss) / P1_THREADS; ++it) {
        const int idx = tid + it * P1_THREADS;
        const int r = idx >> 8, s = idx & 255;
        int bg = b0 + r; if (bg >= Bb) bg = Bb - 1;
        const float2 p = *reinterpret_cast<const float2*>(
            &x[((size_t)bg * Ss + s) * (size_t)Tt + 2 * tp]);
        xs[r * 256 + s]            = p.x;
        xs[MB * 256 + r * 256 + s] = p.y;
    }

    float acc[2][14][2];
#pragma unroll
    for (int tt = 0; tt < 2; ++tt)
#pragma unroll
        for (int r = 0; r < 14; ++r) { acc[tt][r][0] = 0.f; acc[tt][r][1] = 0.f; }

    {
        const float4* src = reinterpret_cast<const float4*>(w1);
        uint32_t dst = (uint32_t)__cvta_generic_to_shared(wr);
#pragma unroll
        for (int i = 0; i < (P1_KC * 256 / 4) / P1_THREADS; ++i)
            cpa16(dst + (tid + i * P1_THREADS) * 16, src + tid + i * P1_THREADS);
        cpa_commit();
    }

    for (int c = 0; c < Hh / P1_KC; ++c) {
        cpa_wait0();
        __syncthreads();
        if (c + 1 < Hh / P1_KC) {
            const float4* src = reinterpret_cast<const float4*>(w1 + (c + 1) * P1_KC * 256);
            uint32_t dst = (uint32_t)__cvta_generic_to_shared(wr + ((c + 1) & 1) * P1_KC * 256);
#pragma unroll
            for (int i = 0; i < (P1_KC * 256 / 4) / P1_THREADS; ++i)
                cpa16(dst + (tid + i * P1_THREADS) * 16, src + tid + i * P1_THREADS);
            cpa_commit();
        }
        const float* wc = wr + (c & 1) * P1_KC * 256;
#pragma unroll
        for (int k4 = 0; k4 < P1_KC / 4; ++k4) {
            float2 wk[4];
#pragma unroll
            for (int kk = 0; kk < 4; ++kk)
                wk[kk] = *reinterpret_cast<const float2*>(wc + (k4 * 4 + kk) * 256 + j0);
#pragma unroll
            for (int tt = 0; tt < 2; ++tt)
#pragma unroll
                for (int r = 0; r < 14; ++r) {
                    const float4 p = *reinterpret_cast<const float4*>(
                        xs + tt * MB * 256 + (row0 + r) * 256 + c * P1_KC + k4 * 4);
                    float a0 = acc[tt][r][0], a1 = acc[tt][r][1];
                    a0 = __fmaf_rn(p.x, wk[0].x, a0);  a1 = __fmaf_rn(p.x, wk[0].y, a1);
                    a0 = __fmaf_rn(p.y, wk[1].x, a0);  a1 = __fmaf_rn(p.y, wk[1].y, a1);
                    a0 = __fmaf_rn(p.z, wk[2].x, a0);  a1 = __fmaf_rn(p.z, wk[2].y, a1);
                    a0 = __fmaf_rn(p.w, wk[3].x, a0);  a1 = __fmaf_rn(p.w, wk[3].y, a1);
                    acc[tt][r][0] = a0; acc[tt][r][1] = a1;
                }
        }
    }

#pragma unroll
    for (int tt = 0; tt < 2; ++tt)
#pragma unroll
        for (int r = 0; r < 14; ++r) {
            const int bg = b0 + row0 + r;
            if (bg < Bb)
                *reinterpret_cast<float2*>(
                    &g_P1[((size_t)(2 * tp + tt) * Bb + bg) * Hh + j0]) =
                    make_float2(acc[tt][r][0], acc[tt][r][1]);
        }
}

// ---------------- K3: scan ----------------
__device__ __forceinline__ void stage_w_warp(const __nv_bfloat16* __restrict__ Wg,
                                             int k0, uint32_t wbuf, int wid, int lane) {
#pragma unroll
    for (int i = 0; i < 6; ++i) {
        const int idx = lane + 32 * i;
        const int sp = idx >> 6;
        const int rem = idx & 63;
        const int n = wid * 16 + (rem >> 2);
        const int quad = rem & 3;
        cpa16(wbuf + sp * WSPB + n * WROWB + quad * 16,
              Wg + sp * (Hh * Hh) + n * Hh + k0 + quad * 8);
    }
    cpa_commit();
}

// One mma GEMM + LIF layer. R16: split-0 partial chained over the chunk's two
// k16 halves (one zeroed cp per chunk) -> Kahan once per k32. Splits 1,2
// accumulate in-place as before (reordered within the chunk; scale <=2^-9).
__device__ __forceinline__ void gemm_lif_layer(
    const __nv_bfloat16* __restrict__ Wg,
    const __nv_bfloat16* __restrict__ WgNext,
    const float (&bf)[4],                   // hoisted epilogue biases
    const __nv_bfloat16* tileIn, __nv_bfloat16* tileOut,
    float* __restrict__ u_s, float (&vm)[16],
    uint32_t wr0, int wid, int lane)
{
    float acc0[2][2][4], comp[2][2][4], acc12[2][2][4];
#pragma unroll
    for (int m = 0; m < 2; ++m)
#pragma unroll
        for (int n8 = 0; n8 < 2; ++n8)
#pragma unroll
            for (int i = 0; i < 4; ++i) {
                acc0[m][n8][i] = 0.f; comp[m][n8][i] = 0.f; acc12[m][n8][i] = 0.f;
            }

    const int a_row = lane & 15;
    const int a_kc  = (lane >> 4) << 3;
    const int b_nrow = lane & 7;
    const int b_half = ((lane >> 3) & 1) * 16;

    for (int c = 0; c < NCHUNK; ++c) {
        cpa_wait0();
        __syncwarp();
        if (c + 1 < NCHUNK)         stage_w_warp(Wg,     (c + 1) * KC, wr0 + ((c + 1) & 1) * WCHUNK, wid, lane);
        else if (WgNext != nullptr) stage_w_warp(WgNext, 0,            wr0,                          wid, lane);

        const uint32_t wbuf = wr0 + (c & 1) * WCHUNK;

        // A fragments for both k16 halves of this k32 chunk.
        uint32_t a[2][2][4];   // [kk2][m]
#pragma unroll
        for (int kk2 = 0; kk2 < 2; ++kk2)
#pragma unroll
            for (int m = 0; m < 2; ++m)
                ldsm_x4(a[kk2][m], (uint32_t)__cvta_generic_to_shared(
                    tileIn + (m * 16 + a_row) * AP + (c * KC + kk2 * 16 + a_kc)));

#pragma unroll
        for (int n8 = 0; n8 < 2; ++n8) {
            const int nrow = wid * 16 + n8 * 8 + b_nrow;
            {   // split 0: chained k32 partial, then one Kahan per chunk
                uint32_t b0[2], b1[2];
                ldsm_x2(b0, wbuf + 0 * WSPB + nrow * WROWB + 0  + b_half);
                ldsm_x2(b1, wbuf + 0 * WSPB + nrow * WROWB + 32 + b_half);
#pragma unroll
                for (int m = 0; m < 2; ++m) {
                    float cp[4] = {0.f, 0.f, 0.f, 0.f};
                    mma16816(cp, a[0][m], b0);
                    mma16816(cp, a[1][m], b1);
#pragma unroll
                    for (int i = 0; i < 4; ++i) {
                        const float y  = __fsub_rn(cp[i], comp[m][n8][i]);
                        const float ts = __fadd_rn(acc0[m][n8][i], y);
                        comp[m][n8][i] = __fsub_rn(__fsub_rn(ts, acc0[m][n8][i]), y);
                        acc0[m][n8][i] = ts;
                    }
                }
            }
            {   // split 1 (both k16 halves)
                uint32_t b0[2], b1[2];
                ldsm_x2(b0, wbuf + 1 * WSPB + nrow * WROWB + 0  + b_half);
                ldsm_x2(b1, wbuf + 1 * WSPB + nrow * WROWB + 32 + b_half);
                mma16816(acc12[0][n8], a[0][0], b0);
                mma16816(acc12[1][n8], a[0][1], b0);
                mma16816(acc12[0][n8], a[1][0], b1);
                mma16816(acc12[1][n8], a[1][1], b1);
            }
            {   // split 2 (both k16 halves)
                uint32_t b0[2], b1[2];
                ldsm_x2(b0, wbuf + 2 * WSPB + nrow * WROWB + 0  + b_half);
                ldsm_x2(b1, wbuf + 2 * WSPB + nrow * WROWB + 32 + b_half);
                mma16816(acc12[0][n8], a[0][0], b0);
                mma16816(acc12[1][n8], a[0][1], b0);
                mma16816(acc12[0][n8], a[1][0], b1);
                mma16816(acc12[1][n8], a[1][1], b1);
            }
        }
    }

#pragma unroll
    for (int m = 0; m < 2; ++m)
#pragma unroll
        for (int n8 = 0; n8 < 2; ++n8)
#pragma unroll
            for (int i = 0; i < 4; ++i) {
                const int row = m * 16 + (lane >> 2) + ((i & 2) ? 8 : 0);
                const int col = wid * 16 + n8 * 8 + (lane & 3) * 2 + (i & 1);
                const int vi  = (m * 2 + n8) * 4 + i;
                const float small = __fsub_rn(acc12[m][n8][i], comp[m][n8][i]);
                const float dot   = __fadd_rn(acc0[m][n8][i], small);
                const float u  = u_s[row * 256 + col];
                const float cur  = __fadd_rn(__fadd_rn(__fmul_rn(u, CDECAY), dot),
                                             bf[n8 * 2 + (i & 1)]);
                const float volt = __fadd_rn(vm[vi], cur);
                const float s    = (volt > VTH) ? 1.0f : 0.0f;
                u_s[row * 256 + col] = cur;
                vm[vi] = __fmul_rn(__fmul_rn(volt, VDECAY), __fsub_rn(1.0f, s));
                tileOut[row * AP + col] = __float2bfloat16(s);
            }
}

__global__ void __launch_bounds__(SC_THREADS, 1) snn_scan(
    const float* __restrict__ b1, const float* __restrict__ b2,
    const float* __restrict__ b3,
    const float* __restrict__ w4, const float* __restrict__ b4,
    float* __restrict__ out)
{
    extern __shared__ char smem[];
    __nv_bfloat16* tileA = reinterpret_cast<__nv_bfloat16*>(smem + OFF_TA);
    __nv_bfloat16* tileB = reinterpret_cast<__nv_bfloat16*>(smem + OFF_TB);
    float* u2s = reinterpret_cast<float*>(smem + OFF_U2);
    float* u3s = reinterpret_cast<float*>(smem + OFF_U3);
    float* w4s = reinterpret_cast<float*>(smem + OFF_W4S);
    const uint32_t wr0 = (uint32_t)__cvta_generic_to_shared(smem + OFF_WR);

    const int tid  = threadIdx.x;
    const int wid  = tid >> 5;
    const int lane = tid & 31;
    const int b0   = blockIdx.x * MB;

    for (int i = tid; i < 32 * 256; i += SC_THREADS) { u2s[i] = 0.0f; u3s[i] = 0.0f; }
    for (int i = tid; i < 32 * AP; i += SC_THREADS) {
        tileA[i] = __float2bfloat16(0.0f);
        tileB[i] = __float2bfloat16(0.0f);
    }
    w4s[tid] = __ldg(w4 + tid);   // Hh*Aa == 512 == SC_THREADS

    float vm1[14], u1[14], vm2[16], vm3[16];
#pragma unroll
    for (int i = 0; i < 14; ++i) { vm1[i] = 0.0f; u1[i] = 0.0f; }
#pragma unroll
    for (int i = 0; i < 16; ++i) { vm2[i] = 0.0f; vm3[i] = 0.0f; }

    // Hoisted epilogue biases for L2/L3 (cols fixed per thread).
    float bf2[4], bf3[4];
#pragma unroll
    for (int n8 = 0; n8 < 2; ++n8)
#pragma unroll
        for (int p = 0; p < 2; ++p) {
            const int col = wid * 16 + n8 * 8 + (lane & 3) * 2 + p;
            bf2[n8 * 2 + p] = __ldg(b2 + col);
            bf3[n8 * 2 + p] = __ldg(b3 + col);
        }

    const int j    = tid & 255;
    const int half = tid >> 8;
    const float bias1 = __ldg(b1 + j);

    const int l4b = tid >> 1, l4a = tid & 1;
    float u4 = 0.f, v4m = 0.f, s4sum = 0.f, bias4 = 0.f;
    if (tid < MB * Aa) bias4 = __ldg(b4 + l4a);

    stage_w_warp(&g_Ws[0][0][0], 0, wr0, wid, lane);
    __syncthreads();

    for (int t = 0; t < Tt; ++t) {
        __nv_bfloat16* bufIn  = (t & 1) ? tileB : tileA;
        __nv_bfloat16* bufTmp = (t & 1) ? tileA : tileB;

        // ---- L1 (exact): cur = u*0.5 + P1 + b1
#pragma unroll
        for (int r = 0; r < 14; ++r) {
            const int row = half * 14 + r;
            int bg = b0 + row; if (bg >= Bb) bg = Bb - 1;
            const float p = ldcs1(&g_P1[((size_t)t * Bb + bg) * Hh + j]);
            const float cur  = __fadd_rn(__fadd_rn(__fmul_rn(u1[r], CDECAY), p), bias1);
            const float volt = __fadd_rn(vm1[r], cur);
            const float s    = (volt > VTH) ? 1.0f : 0.0f;
            u1[r] = cur;
            vm1[r] = __fmul_rn(__fmul_rn(volt, VDECAY), __fsub_rn(1.0f, s));
            bufIn[row * AP + j] = __float2bfloat16(s);
        }
        __syncthreads();   // s1 visible; prior L4 done with bufTmp

        gemm_lif_layer(&g_Ws[0][0][0], &g_Ws[1][0][0], bf2,
                       bufIn, bufTmp, u2s, vm2, wr0, wid, lane);
        __syncthreads();   // s2 visible

        gemm_lif_layer(&g_Ws[1][0][0], (t + 1 < Tt) ? &g_Ws[0][0][0] : nullptr, bf3,
                       bufTmp, bufIn, u3s, vm3, wr0, wid, lane);
        __syncthreads();   // s3 (bufIn) visible to L4

        // ---- L4 (exact): [MB,256]@[256,2] + LIF  (no trailing barrier)
        if (tid < MB * Aa) {
            float acc = 0.0f;
            const __nv_bfloat16* row4 = bufIn + l4b * AP;
#pragma unroll 8
            for (int k = 0; k < Hh; ++k)
                acc = __fmaf_rn(__bfloat162float(row4[k]), w4s[k * Aa + l4a], acc);
            const float cur  = __fadd_rn(__fadd_rn(__fmul_rn(u4, CDECAY), acc), bias4);
            const float volt = __fadd_rn(v4m, cur);
            const float s    = (volt > VTH) ? 1.0f : 0.0f;
            u4 = cur;
            v4m = __fmul_rn(__fmul_rn(volt, VDECAY), __fsub_rn(1.0f, s));
            s4sum = __fadd_rn(s4sum, s);
        }
    }

    if (tid < MB * Aa) {
        const int bg = b0 + l4b;
        if (bg < Bb)
            out[bg * Aa + l4a] = __fdiv_rn(__fdiv_rn(s4sum, (float)Tt), (float)Tt);
    }
}

extern "C" void kernel_launch(void* const* d_in, const int* in_sizes, int n_in,
                              void* d_out, int out_size)
{
    const float* x  = (const float*)d_in[0];
    const float* w1 = (const float*)d_in[1];
    const float* b1 = (const float*)d_in[2];
    const float* w2 = (const float*)d_in[3];
    const float* b2 = (const float*)d_in[4];
    const float* w3 = (const float*)d_in[5];
    const float* b3 = (const float*)d_in[6];
    const float* w4 = (const float*)d_in[7];
    const float* b4 = (const float*)d_in[8];
    float* out = (float*)d_out;
    (void)in_sizes; (void)n_in; (void)out_size;

    cudaFuncSetAttribute(p1_gemm,  cudaFuncAttributeMaxDynamicSharedMemorySize, P1_SMEM);
    cudaFuncSetAttribute(snn_scan, cudaFuncAttributeMaxDynamicSharedMemorySize, SC_SMEM);

    split_w<<<dim3((Hh * Hh + 255) / 256, 2), 256>>>(w2, w3);
    p1_gemm<<<dim3(NBLK, Tt / 2), P1_THREADS, P1_SMEM>>>(x, w1);
    snn_scan<<<NBLK, SC_THREADS, SC_SMEM>>>(b1, b2, b3, w4, b4, out);
}